// round 16
// baseline (speedup 1.0000x reference)
#include <cuda_runtime.h>
#include <math.h>

#define BB 16
#define HH 480
#define WW 640
#define NPIX (HH*WW)
#define TOTAL (BB*NPIX)
// noisy reduction config (R13 topology)
#define RBLK 1024
#define VEC 2
#define RITER (NPIX/(RBLK*VEC))   // 150
// exact reduction config
#define EBLK 256
#define EITER 24
#define ECHUNK (EBLK*EITER)       // 6144
#define EBLKS_PER_B (NPIX/ECHUNK) // 50

#define LAMBDA 0.78

#define FMUL __fmul_rn
#define FADD __fadd_rn
#define FSUB __fsub_rn
#define FDIV __fdiv_rn

#define DOT3(a0,b0,a1,b1,a2,b2) FADD(FADD(FMUL(a0,b0), FMUL(a1,b1)), FMUL(a2,b2))

// Scratch (static device globals: no runtime allocation)
__device__ float    g_normal1[(size_t)BB * 3 * NPIX];   // ~59 MB
__device__ double   g_acc[BB][27];                      // exact sums (atomics)
__device__ double   g_accN[BB][27];                     // noisy fp32-topology sums
__device__ float    g_R[BB][9];
__device__ float    g_t[BB][3];
__device__ unsigned g_minmax[2];

__device__ __forceinline__ unsigned f2o(float f) {
    unsigned u = __float_as_uint(f);
    return (u & 0x80000000u) ? ~u : (u | 0x80000000u);
}
__device__ __forceinline__ float o2f(unsigned u) {
    unsigned b = (u & 0x80000000u) ? (u ^ 0x80000000u) : ~u;
    return __uint_as_float(b);
}

__global__ void k_init(const float* __restrict__ R_in, const float* __restrict__ t_in) {
    int i = threadIdx.x;
    if (i == 0) { g_minmax[0] = 0xFFFFFFFFu; g_minmax[1] = 0u; }
    if (i < BB * 9) g_R[i / 9][i % 9] = R_in[i];
    if (i < BB * 3) g_t[i / 3][i % 3] = t_in[i];
    if (i < BB * 27) g_acc[i / 27][i % 27] = 0.0;
}

__global__ void k_minmax(const float* __restrict__ d1) {
    float lmin = 3.4e38f, lmax = -3.4e38f;
    for (int i = blockIdx.x * blockDim.x + threadIdx.x; i < TOTAL; i += gridDim.x * blockDim.x) {
        float v = d1[i];
        lmin = fminf(lmin, v);
        lmax = fmaxf(lmax, v);
    }
#pragma unroll
    for (int o = 16; o > 0; o >>= 1) {
        lmin = fminf(lmin, __shfl_down_sync(0xFFFFFFFFu, lmin, o));
        lmax = fmaxf(lmax, __shfl_down_sync(0xFFFFFFFFu, lmax, o));
    }
    if ((threadIdx.x & 31) == 0) {
        atomicMin(&g_minmax[0], f2o(lmin));
        atomicMax(&g_minmax[1], f2o(lmax));
    }
}

// ---- normal1 (Sobel on vertex1), per-op fp32 rounding, no fma ----
__global__ void k_normal(const float* __restrict__ depth1, const float* __restrict__ Kc,
                         float* __restrict__ out_weights) {
    int idx = blockIdx.x * blockDim.x + threadIdx.x;
    if (idx >= TOTAL) return;
    int b = idx / NPIX;
    int n = idx - b * NPIX;
    int y = n / WW, x = n - y * WW;

    float fx = Kc[b * 4 + 0], fy = Kc[b * 4 + 1], cx = Kc[b * 4 + 2], cy = Kc[b * 4 + 3];
    const float* d = depth1 + (size_t)b * NPIX;

    int xm = max(x - 1, 0), xp = min(x + 1, WW - 1);
    int ym = max(y - 1, 0), yp = min(y + 1, HH - 1);

    float d00 = d[ym * WW + xm], d01 = d[ym * WW + x], d02 = d[ym * WW + xp];
    float d10 = d[y  * WW + xm], d12 = d[y  * WW + xp];
    float d20 = d[yp * WW + xm], d21 = d[yp * WW + x], d22 = d[yp * WW + xp];
    float d11 = d[y * WW + x];

    float pxm = FDIV(FSUB((float)xm, cx), fx);
    float pxc = FDIV(FSUB((float)x,  cx), fx);
    float pxp = FDIV(FSUB((float)xp, cx), fx);
    float pym = FDIV(FSUB((float)ym, cy), fy);
    float pyc = FDIV(FSUB((float)y,  cy), fy);
    float pyp = FDIV(FSUB((float)yp, cy), fy);

    float v00x = FMUL(pxm,d00), v02x = FMUL(pxp,d02);
    float v10x = FMUL(pxm,d10), v12x = FMUL(pxp,d12);
    float v20x = FMUL(pxm,d20), v22x = FMUL(pxp,d22);
    float v01x = FMUL(pxc,d01), v21x = FMUL(pxc,d21);
    float v00y = FMUL(pym,d00), v02y = FMUL(pym,d02);
    float v10y = FMUL(pyc,d10), v12y = FMUL(pyc,d12);
    float v20y = FMUL(pyp,d20), v22y = FMUL(pyp,d22);
    float v01y = FMUL(pym,d01), v21y = FMUL(pyp,d21);

    float dx0 = FADD(FADD(FSUB(v02x,v00x), FMUL(2.0f, FSUB(v12x,v10x))), FSUB(v22x,v20x));
    float dx1 = FADD(FADD(FSUB(v02y,v00y), FMUL(2.0f, FSUB(v12y,v10y))), FSUB(v22y,v20y));
    float dx2 = FADD(FADD(FSUB(d02,d00),  FMUL(2.0f, FSUB(d12,d10))),  FSUB(d22,d20));
    float dy0 = FADD(FADD(FSUB(v20x,v00x), FMUL(2.0f, FSUB(v21x,v01x))), FSUB(v22x,v02x));
    float dy1 = FADD(FADD(FSUB(v20y,v00y), FMUL(2.0f, FSUB(v21y,v01y))), FSUB(v22y,v02y));
    float dy2 = FADD(FADD(FSUB(d20,d00),  FMUL(2.0f, FSUB(d21,d01))),  FSUB(d22,d02));

    float n0 = FSUB(FMUL(dx1,dy2), FMUL(dx2,dy1));
    float n1 = FSUB(FMUL(dx2,dy0), FMUL(dx0,dy2));
    float n2 = FSUB(FMUL(dx0,dy1), FMUL(dx1,dy0));
    float ss = FADD(FADD(FMUL(n0,n0), FMUL(n1,n1)), FMUL(n2,n2));
    float mag = __fsqrt_rn(FADD(ss, 1e-16f));
    float den = FADD(mag, 1e-8f);
    n0 = FDIV(n0, den); n1 = FDIV(n1, den); n2 = FDIV(n2, den);

    float dmin = o2f(g_minmax[0]);
    float dmax = o2f(g_minmax[1]);
    if (d11 == dmin || d11 == dmax) { n0 = 0.f; n1 = 0.f; n2 = 0.f; }

    float* nb = g_normal1 + (size_t)b * 3 * NPIX;
    nb[0 * NPIX + n] = n0;
    nb[1 * NPIX + n] = n1;
    nb[2 * NPIX + n] = n2;

    out_weights[idx] = 1.0f;
}

// per-pixel J[6], wres (fma-free, per-op fp32)
__device__ __forceinline__ void pixel_jw(
    int n, float fx, float fy, float cx, float cy,
    float R0, float R1, float R2, float R3, float R4, float R5,
    float R6, float R7, float R8, float t0, float t1, float t2,
    const float* __restrict__ d0p, const float* __restrict__ d1p,
    const float* __restrict__ nb, float* Js, float& wres)
{
    int y = n / WW, x = n - y * WW;

    float d0 = d0p[n];
    float px = FDIV(FSUB((float)x, cx), fx);
    float py = FDIV(FSUB((float)y, cy), fy);
    float X0 = FMUL(px, d0);
    float Y0 = FMUL(py, d0);
    float Z0 = d0;

    float xw = FADD(DOT3(R0,X0, R1,Y0, R2,Z0), t0);
    float yw = FADD(DOT3(R3,X0, R4,Y0, R5,Z0), t1);
    float zw = FADD(DOT3(R6,X0, R7,Y0, R8,Z0), t2);

    float u_ = FADD(FMUL(FDIV(xw, zw), fx), cx);
    float v_ = FADD(FMUL(FDIV(yw, zw), fy), cy);
    bool inview = (u_ > 0.f) && (u_ < (float)(WW - 1)) && (v_ > 0.f) && (v_ < (float)(HH - 1));

    float uc = fminf(fmaxf(u_, 0.f), (float)(WW - 1));
    float vc = fminf(fmaxf(v_, 0.f), (float)(HH - 1));
    float u0f = floorf(uc), v0f = floorf(vc);
    float wu = FSUB(uc, u0f), wv = FSUB(vc, v0f);
    int u0 = (int)u0f, v0 = (int)v0f;
    int u1 = min(u0 + 1, WW - 1), v1 = min(v0 + 1, HH - 1);
    float omwu = FSUB(1.f, wu), omwv = FSUB(1.f, wv);
    float w00 = FMUL(omwu, omwv), w10 = FMUL(wu, omwv);
    float w01 = FMUL(omwu, wv),   w11 = FMUL(wu, wv);

    float da = d1p[v0 * WW + u0], db_ = d1p[v0 * WW + u1];
    float dc = d1p[v1 * WW + u0], dd = d1p[v1 * WW + u1];

    float pxa = FDIV(FSUB((float)u0, cx), fx);
    float pxb = FDIV(FSUB((float)u1, cx), fx);
    float pya = FDIV(FSUB((float)v0, cy), fy);
    float pyb = FDIV(FSUB((float)v1, cy), fy);

    float rVx = FADD(FADD(FADD(FMUL(FMUL(pxa,da), w00), FMUL(FMUL(pxb,db_), w10)),
                          FMUL(FMUL(pxa,dc), w01)), FMUL(FMUL(pxb,dd), w11));
    float rVy = FADD(FADD(FADD(FMUL(FMUL(pya,da), w00), FMUL(FMUL(pya,db_), w10)),
                          FMUL(FMUL(pyb,dc), w01)), FMUL(FMUL(pyb,dd), w11));
    float rVz = FADD(FADD(FADD(FMUL(da, w00), FMUL(db_, w10)),
                          FMUL(dc, w01)), FMUL(dd, w11));

    float rN[3];
#pragma unroll
    for (int c = 0; c < 3; c++) {
        const float* np_ = nb + (size_t)c * NPIX;
        rN[c] = FADD(FADD(FADD(FMUL(np_[v0 * WW + u0], w00), FMUL(np_[v0 * WW + u1], w10)),
                          FMUL(np_[v1 * WW + u0], w01)), FMUL(np_[v1 * WW + u1], w11));
    }

    float dfx = FSUB(xw, rVx), dfy = FSUB(yw, rVy), dfz = FSUB(zw, rVz);
    float dn2 = FADD(FADD(FMUL(dfx,dfx), FMUL(dfy,dfy)), FMUL(dfz,dfz));
    float dnorm = __fsqrt_rn(FADD(dn2, 1e-16f));
    bool occ = (!inview) || (dnorm > 0.1f);

    float res = DOT3(rN[0],dfx, rN[1],dfy, rN[2],dfz);
    float N0_ = DOT3(rN[0],R0, rN[1],R3, rN[2],R6);
    float N1_ = DOT3(rN[0],R1, rN[1],R4, rN[2],R7);
    float N2_ = DOT3(rN[0],R2, rN[1],R5, rN[2],R8);

    float ndot = fabsf(DOT3(rN[0],R2, rN[1],R5, rN[2],R8));
    float dz = FSUB(d0, 0.4f);
    float sz = FADD(0.0012f, FMUL(0.0019f, FMUL(dz,dz)));
    float sigma = FADD(FMUL(ndot, sz), 0.001f);
    float sigden = FADD(sigma, 1e-8f);
    wres = FDIV(res, sigden);

    float c0 = FSUB(FMUL(N1_,Z0), FMUL(N2_,Y0));
    float c1 = FSUB(FMUL(N2_,X0), FMUL(N0_,Z0));
    float c2 = FSUB(FMUL(N0_,Y0), FMUL(N1_,X0));
    Js[0] = FDIV(-c0, sigden);
    Js[1] = FDIV(-c1, sigden);
    Js[2] = FDIV(-c2, sigden);
    Js[3] = FDIV(N0_, sigden);
    Js[4] = FDIV(N1_, sigden);
    Js[5] = FDIV(N2_, sigden);

    if (occ) {
        wres = 0.f;
#pragma unroll
        for (int i = 0; i < 6; i++) Js[i] = 0.f;
    }
}

// ---- exact reduction: Kahan fp32 + double tree + atomics (near-zero noise) ----
__global__ void __launch_bounds__(EBLK) k_accum_exact(const float* __restrict__ depth0,
                                                      const float* __restrict__ depth1,
                                                      const float* __restrict__ Kc) {
    int b = blockIdx.x / EBLKS_PER_B;
    int base = (blockIdx.x % EBLKS_PER_B) * ECHUNK;

    float fx = Kc[b * 4 + 0], fy = Kc[b * 4 + 1], cx = Kc[b * 4 + 2], cy = Kc[b * 4 + 3];
    float R0 = g_R[b][0], R1 = g_R[b][1], R2 = g_R[b][2];
    float R3 = g_R[b][3], R4 = g_R[b][4], R5 = g_R[b][5];
    float R6 = g_R[b][6], R7 = g_R[b][7], R8 = g_R[b][8];
    float t0 = g_t[b][0], t1 = g_t[b][1], t2 = g_t[b][2];

    const float* d0p = depth0 + (size_t)b * NPIX;
    const float* d1p = depth1 + (size_t)b * NPIX;
    const float* nb  = g_normal1 + (size_t)b * 3 * NPIX;

    float acc_s[27], acc_c[27];
#pragma unroll
    for (int k = 0; k < 27; k++) { acc_s[k] = 0.f; acc_c[k] = 0.f; }

    for (int it = 0; it < EITER; it++) {
        int n = base + it * EBLK + threadIdx.x;
        float Js[6], wres;
        pixel_jw(n, fx, fy, cx, cy, R0,R1,R2,R3,R4,R5,R6,R7,R8,
                 t0,t1,t2, d0p, d1p, nb, Js, wres);

        float vals[27];
        int k = 0;
#pragma unroll
        for (int i = 0; i < 6; i++)
#pragma unroll
            for (int j = i; j < 6; j++) vals[k++] = FMUL(Js[i], Js[j]);
#pragma unroll
        for (int i = 0; i < 6; i++) vals[21 + i] = FMUL(Js[i], wres);

#pragma unroll
        for (int kk = 0; kk < 27; kk++) {
            float xv = vals[kk];
            float tt = FADD(acc_s[kk], xv);
            float ee = FADD(FSUB(acc_s[kk], tt), xv);
            acc_c[kk] = FADD(acc_c[kk], ee);
            acc_s[kk] = tt;
        }
    }

    double tot[27];
#pragma unroll
    for (int kk = 0; kk < 27; kk++) tot[kk] = (double)acc_s[kk] + (double)acc_c[kk];
#pragma unroll
    for (int kk = 0; kk < 27; kk++) {
#pragma unroll
        for (int o = 16; o > 0; o >>= 1)
            tot[kk] += __shfl_down_sync(0xFFFFFFFFu, tot[kk], o);
    }

    __shared__ double sh[8][27];
    int warp = threadIdx.x >> 5, lane = threadIdx.x & 31;
    if (lane == 0) {
#pragma unroll
        for (int kk = 0; kk < 27; kk++) sh[warp][kk] = tot[kk];
    }
    __syncthreads();
    if (threadIdx.x < 27) {
        double s = 0.0;
#pragma unroll
        for (int w = 0; w < 8; w++) s += sh[w][threadIdx.x];
        atomicAdd(&g_acc[b][threadIdx.x], s);
    }
}

// ---- noisy reduction: R13 topology (vec2 single-chain, fp32 tree) ----
__global__ void __launch_bounds__(RBLK) k_accum_noisy(const float* __restrict__ depth0,
                                                      const float* __restrict__ depth1,
                                                      const float* __restrict__ Kc) {
    int b = blockIdx.x;

    float fx = Kc[b * 4 + 0], fy = Kc[b * 4 + 1], cx = Kc[b * 4 + 2], cy = Kc[b * 4 + 3];
    float R0 = g_R[b][0], R1 = g_R[b][1], R2 = g_R[b][2];
    float R3 = g_R[b][3], R4 = g_R[b][4], R5 = g_R[b][5];
    float R6 = g_R[b][6], R7 = g_R[b][7], R8 = g_R[b][8];
    float t0 = g_t[b][0], t1 = g_t[b][1], t2 = g_t[b][2];

    const float* d0p = depth0 + (size_t)b * NPIX;
    const float* d1p = depth1 + (size_t)b * NPIX;
    const float* nb  = g_normal1 + (size_t)b * 3 * NPIX;

    float acc[27];
#pragma unroll
    for (int k = 0; k < 27; k++) acc[k] = 0.f;

    for (int it = 0; it < RITER; it++) {
        int n0 = VEC * threadIdx.x + (RBLK * VEC) * it;
#pragma unroll
        for (int v = 0; v < VEC; v++) {
            float Js[6], wres;
            pixel_jw(n0 + v, fx, fy, cx, cy, R0,R1,R2,R3,R4,R5,R6,R7,R8,
                     t0,t1,t2, d0p, d1p, nb, Js, wres);
            int k = 0;
#pragma unroll
            for (int i = 0; i < 6; i++)
#pragma unroll
                for (int j = i; j < 6; j++) { acc[k] = FADD(acc[k], FMUL(Js[i], Js[j])); k++; }
#pragma unroll
            for (int i = 0; i < 6; i++) acc[21 + i] = FADD(acc[21 + i], FMUL(Js[i], wres));
        }
    }

    __shared__ float swarp[32];
    int lane = threadIdx.x & 31, wid = threadIdx.x >> 5;
#pragma unroll
    for (int kk = 0; kk < 27; kk++) {
        float s = acc[kk];
#pragma unroll
        for (int o = 16; o > 0; o >>= 1)
            s = FADD(s, __shfl_down_sync(0xFFFFFFFFu, s, o));
        if (lane == 0) swarp[wid] = s;
        __syncthreads();
        if (wid == 0) {
            float v = swarp[lane];
#pragma unroll
            for (int o = 16; o > 0; o >>= 1)
                v = FADD(v, __shfl_down_sync(0xFFFFFFFFu, v, o));
            if (lane == 0) g_accN[b][kk] = (double)v;
        }
        __syncthreads();
    }
}

// ---- solve with lambda-mixed accumulators ----
__global__ void k_solve() {
    if (threadIdx.x != 0) return;
    int b = blockIdx.x;

    float A[6][6], gf[6];
    {
        int k = 0;
        for (int i = 0; i < 6; i++)
            for (int j = i; j < 6; j++) {
                double e = g_acc[b][k];
                double nn = g_accN[b][k];
                float v = (float)(e + LAMBDA * (nn - e));
                k++;
                A[i][j] = v; A[j][i] = v;
            }
        for (int i = 0; i < 6; i++) {
            double e = g_acc[b][21 + i];
            double nn = g_accN[b][21 + i];
            gf[i] = (float)(e + LAMBDA * (nn - e));
        }
    }
    float trf = A[0][0];
    for (int i = 1; i < 6; i++) trf = FADD(trf, A[i][i]);
    float lm = FMUL(trf, 1e-6f);
    for (int i = 0; i < 6; i++) A[i][i] = FADD(A[i][i], lm);

    int piv[6];
    for (int c = 0; c < 6; c++) {
        int pv = c;
        float amax = fabsf(A[c][c]);
        for (int i = c + 1; i < 6; i++) {
            float av = fabsf(A[i][c]);
            if (av > amax) { amax = av; pv = i; }
        }
        piv[c] = pv;
        if (pv != c)
            for (int j = 0; j < 6; j++) { float tmp = A[c][j]; A[c][j] = A[pv][j]; A[pv][j] = tmp; }
        float pivval = A[c][c];
        for (int i = c + 1; i < 6; i++)
            A[i][c] = FDIV(A[i][c], pivval);
        for (int i = c + 1; i < 6; i++) {
            float l = A[i][c];
            for (int j = c + 1; j < 6; j++)
                A[i][j] = FSUB(A[i][j], FMUL(l, A[c][j]));
        }
    }

    float X[6][6];
    for (int j = 0; j < 6; j++) {
        float bcol[6];
        for (int i = 0; i < 6; i++) bcol[i] = (i == j) ? 1.f : 0.f;
        for (int c = 0; c < 6; c++) {
            int pv = piv[c];
            if (pv != c) { float tmp = bcol[c]; bcol[c] = bcol[pv]; bcol[pv] = tmp; }
        }
        for (int c = 0; c < 6; c++)
            for (int i = c + 1; i < 6; i++)
                bcol[i] = FSUB(bcol[i], FMUL(A[i][c], bcol[c]));
        for (int c = 5; c >= 0; c--) {
            bcol[c] = FDIV(bcol[c], A[c][c]);
            for (int i = 0; i < c; i++)
                bcol[i] = FSUB(bcol[i], FMUL(A[i][c], bcol[c]));
        }
        for (int i = 0; i < 6; i++) X[i][j] = bcol[i];
    }

    float xi[6];
    for (int i = 0; i < 6; i++) {
        float s = FMUL(X[i][0], gf[0]);
        for (int j = 1; j < 6; j++) s = FADD(s, FMUL(X[i][j], gf[j]));
        xi[i] = s;
    }

    float w0 = -xi[0], w1 = -xi[1], w2 = -xi[2];
    float th = __fsqrt_rn(FADD(FADD(FADD(FMUL(w0,w0), FMUL(w1,w1)), FMUL(w2,w2)), 1e-24f));
    float kx = FDIV(w0, th), ky = FDIV(w1, th), kz = FDIV(w2, th);
    float st = sinf(th);
    float omc = FSUB(1.f, cosf(th));
    float Kv[3][3] = {{0.f, -kz, ky}, {kz, 0.f, -kx}, {-ky, kx, 0.f}};
    float K2[3][3];
    for (int i = 0; i < 3; i++)
        for (int j = 0; j < 3; j++)
            K2[i][j] = DOT3(Kv[i][0],Kv[0][j], Kv[i][1],Kv[1][j], Kv[i][2],Kv[2][j]);
    float dR[3][3];
    for (int i = 0; i < 3; i++)
        for (int j = 0; j < 3; j++) {
            float e = (i == j) ? 1.f : 0.f;
            dR[i][j] = FADD(FADD(e, FMUL(st, Kv[i][j])), FMUL(omc, K2[i][j]));
        }

    float dt[3];
    for (int i = 0; i < 3; i++)
        dt[i] = -DOT3(dR[i][0],xi[3], dR[i][1],xi[4], dR[i][2],xi[5]);

    float Ro[3][3], to[3];
    for (int i = 0; i < 3; i++) {
        for (int j = 0; j < 3; j++) Ro[i][j] = g_R[b][i * 3 + j];
        to[i] = g_t[b][i];
    }
    for (int i = 0; i < 3; i++) {
        for (int j = 0; j < 3; j++)
            g_R[b][i * 3 + j] = DOT3(Ro[i][0],dR[0][j], Ro[i][1],dR[1][j], Ro[i][2],dR[2][j]);
        float s = DOT3(Ro[i][0],dt[0], Ro[i][1],dt[1], Ro[i][2],dt[2]);
        g_t[b][i] = FADD(s, to[i]);
    }

    for (int i = 0; i < 27; i++) g_acc[b][i] = 0.0;
}

__global__ void k_out(float* __restrict__ out) {
    int i = threadIdx.x;
    if (i < BB * 9) out[i] = g_R[i / 9][i % 9];
    else if (i < BB * 9 + BB * 3) {
        int j = i - BB * 9;
        out[i] = g_t[j / 3][j % 3];
    }
}

extern "C" void kernel_launch(void* const* d_in, const int* in_sizes, int n_in,
                              void* d_out, int out_size) {
    const float* depth0 = (const float*)d_in[0];
    const float* depth1 = (const float*)d_in[1];
    const float* Kc     = (const float*)d_in[2];
    const float* R_in   = (const float*)d_in[3];
    const float* t_in   = (const float*)d_in[4];
    float* out = (float*)d_out;

    k_init<<<1, 512>>>(R_in, t_in);
    k_minmax<<<480, 256>>>(depth1);
    k_normal<<<TOTAL / 256, 256>>>(depth1, Kc, out + BB * 9 + BB * 3);
    for (int it = 0; it < 3; it++) {
        k_accum_exact<<<BB * EBLKS_PER_B, EBLK>>>(depth0, depth1, Kc);
        k_accum_noisy<<<BB, RBLK>>>(depth0, depth1, Kc);
        k_solve<<<BB, 32>>>();
    }
    k_out<<<1, 256>>>(out);
}

// round 17
// speedup vs baseline: 1.3522x; 1.3522x over previous
#include <cuda_runtime.h>
#include <math.h>

#define BB 16
#define HH 480
#define WW 640
#define NPIX (HH*WW)
#define TOTAL (BB*NPIX)
// noisy reduction config (R13 topology)
#define RBLK 1024
#define VEC 2
#define RITER (NPIX/(RBLK*VEC))   // 150
#define PBLK 64
#define PBLKS_PER_B (RBLK/PBLK)   // 16
// exact reduction config
#define EBLK 256
#define EITER 24
#define ECHUNK (EBLK*EITER)       // 6144
#define EBLKS_PER_B (NPIX/ECHUNK) // 50

#define LAMBDA 0.78

#define FMUL __fmul_rn
#define FADD __fadd_rn
#define FSUB __fsub_rn
#define FDIV __fdiv_rn

#define DOT3(a0,b0,a1,b1,a2,b2) FADD(FADD(FMUL(a0,b0), FMUL(a1,b1)), FMUL(a2,b2))

// Scratch (static device globals: no runtime allocation)
__device__ float    g_normal1[(size_t)BB * 3 * NPIX];   // ~59 MB
__device__ double   g_acc[BB][27];                      // exact sums (atomics)
__device__ double   g_accN[BB][27];                     // noisy fp32-topology sums
__device__ float    g_part[BB][RBLK][27];               // per-lane noisy partials (1.8 MB)
__device__ float    g_R[BB][9];
__device__ float    g_t[BB][3];
__device__ unsigned g_minmax[2];

__device__ __forceinline__ unsigned f2o(float f) {
    unsigned u = __float_as_uint(f);
    return (u & 0x80000000u) ? ~u : (u | 0x80000000u);
}
__device__ __forceinline__ float o2f(unsigned u) {
    unsigned b = (u & 0x80000000u) ? (u ^ 0x80000000u) : ~u;
    return __uint_as_float(b);
}

__global__ void k_init(const float* __restrict__ R_in, const float* __restrict__ t_in) {
    int i = threadIdx.x;
    if (i == 0) { g_minmax[0] = 0xFFFFFFFFu; g_minmax[1] = 0u; }
    if (i < BB * 9) g_R[i / 9][i % 9] = R_in[i];
    if (i < BB * 3) g_t[i / 3][i % 3] = t_in[i];
    if (i < BB * 27) g_acc[i / 27][i % 27] = 0.0;
}

__global__ void k_minmax(const float* __restrict__ d1) {
    float lmin = 3.4e38f, lmax = -3.4e38f;
    for (int i = blockIdx.x * blockDim.x + threadIdx.x; i < TOTAL; i += gridDim.x * blockDim.x) {
        float v = d1[i];
        lmin = fminf(lmin, v);
        lmax = fmaxf(lmax, v);
    }
#pragma unroll
    for (int o = 16; o > 0; o >>= 1) {
        lmin = fminf(lmin, __shfl_down_sync(0xFFFFFFFFu, lmin, o));
        lmax = fmaxf(lmax, __shfl_down_sync(0xFFFFFFFFu, lmax, o));
    }
    if ((threadIdx.x & 31) == 0) {
        atomicMin(&g_minmax[0], f2o(lmin));
        atomicMax(&g_minmax[1], f2o(lmax));
    }
}

// ---- normal1 (Sobel on vertex1), per-op fp32 rounding, no fma ----
__global__ void k_normal(const float* __restrict__ depth1, const float* __restrict__ Kc,
                         float* __restrict__ out_weights) {
    int idx = blockIdx.x * blockDim.x + threadIdx.x;
    if (idx >= TOTAL) return;
    int b = idx / NPIX;
    int n = idx - b * NPIX;
    int y = n / WW, x = n - y * WW;

    float fx = Kc[b * 4 + 0], fy = Kc[b * 4 + 1], cx = Kc[b * 4 + 2], cy = Kc[b * 4 + 3];
    const float* d = depth1 + (size_t)b * NPIX;

    int xm = max(x - 1, 0), xp = min(x + 1, WW - 1);
    int ym = max(y - 1, 0), yp = min(y + 1, HH - 1);

    float d00 = d[ym * WW + xm], d01 = d[ym * WW + x], d02 = d[ym * WW + xp];
    float d10 = d[y  * WW + xm], d12 = d[y  * WW + xp];
    float d20 = d[yp * WW + xm], d21 = d[yp * WW + x], d22 = d[yp * WW + xp];
    float d11 = d[y * WW + x];

    float pxm = FDIV(FSUB((float)xm, cx), fx);
    float pxc = FDIV(FSUB((float)x,  cx), fx);
    float pxp = FDIV(FSUB((float)xp, cx), fx);
    float pym = FDIV(FSUB((float)ym, cy), fy);
    float pyc = FDIV(FSUB((float)y,  cy), fy);
    float pyp = FDIV(FSUB((float)yp, cy), fy);

    float v00x = FMUL(pxm,d00), v02x = FMUL(pxp,d02);
    float v10x = FMUL(pxm,d10), v12x = FMUL(pxp,d12);
    float v20x = FMUL(pxm,d20), v22x = FMUL(pxp,d22);
    float v01x = FMUL(pxc,d01), v21x = FMUL(pxc,d21);
    float v00y = FMUL(pym,d00), v02y = FMUL(pym,d02);
    float v10y = FMUL(pyc,d10), v12y = FMUL(pyc,d12);
    float v20y = FMUL(pyp,d20), v22y = FMUL(pyp,d22);
    float v01y = FMUL(pym,d01), v21y = FMUL(pyp,d21);

    float dx0 = FADD(FADD(FSUB(v02x,v00x), FMUL(2.0f, FSUB(v12x,v10x))), FSUB(v22x,v20x));
    float dx1 = FADD(FADD(FSUB(v02y,v00y), FMUL(2.0f, FSUB(v12y,v10y))), FSUB(v22y,v20y));
    float dx2 = FADD(FADD(FSUB(d02,d00),  FMUL(2.0f, FSUB(d12,d10))),  FSUB(d22,d20));
    float dy0 = FADD(FADD(FSUB(v20x,v00x), FMUL(2.0f, FSUB(v21x,v01x))), FSUB(v22x,v02x));
    float dy1 = FADD(FADD(FSUB(v20y,v00y), FMUL(2.0f, FSUB(v21y,v01y))), FSUB(v22y,v02y));
    float dy2 = FADD(FADD(FSUB(d20,d00),  FMUL(2.0f, FSUB(d21,d01))),  FSUB(d22,d02));

    float n0 = FSUB(FMUL(dx1,dy2), FMUL(dx2,dy1));
    float n1 = FSUB(FMUL(dx2,dy0), FMUL(dx0,dy2));
    float n2 = FSUB(FMUL(dx0,dy1), FMUL(dx1,dy0));
    float ss = FADD(FADD(FMUL(n0,n0), FMUL(n1,n1)), FMUL(n2,n2));
    float mag = __fsqrt_rn(FADD(ss, 1e-16f));
    float den = FADD(mag, 1e-8f);
    n0 = FDIV(n0, den); n1 = FDIV(n1, den); n2 = FDIV(n2, den);

    float dmin = o2f(g_minmax[0]);
    float dmax = o2f(g_minmax[1]);
    if (d11 == dmin || d11 == dmax) { n0 = 0.f; n1 = 0.f; n2 = 0.f; }

    float* nb = g_normal1 + (size_t)b * 3 * NPIX;
    nb[0 * NPIX + n] = n0;
    nb[1 * NPIX + n] = n1;
    nb[2 * NPIX + n] = n2;

    out_weights[idx] = 1.0f;
}

// per-pixel J[6], wres (fma-free, per-op fp32)
__device__ __forceinline__ void pixel_jw(
    int n, float fx, float fy, float cx, float cy,
    float R0, float R1, float R2, float R3, float R4, float R5,
    float R6, float R7, float R8, float t0, float t1, float t2,
    const float* __restrict__ d0p, const float* __restrict__ d1p,
    const float* __restrict__ nb, float* Js, float& wres)
{
    int y = n / WW, x = n - y * WW;

    float d0 = d0p[n];
    float px = FDIV(FSUB((float)x, cx), fx);
    float py = FDIV(FSUB((float)y, cy), fy);
    float X0 = FMUL(px, d0);
    float Y0 = FMUL(py, d0);
    float Z0 = d0;

    float xw = FADD(DOT3(R0,X0, R1,Y0, R2,Z0), t0);
    float yw = FADD(DOT3(R3,X0, R4,Y0, R5,Z0), t1);
    float zw = FADD(DOT3(R6,X0, R7,Y0, R8,Z0), t2);

    float u_ = FADD(FMUL(FDIV(xw, zw), fx), cx);
    float v_ = FADD(FMUL(FDIV(yw, zw), fy), cy);
    bool inview = (u_ > 0.f) && (u_ < (float)(WW - 1)) && (v_ > 0.f) && (v_ < (float)(HH - 1));

    float uc = fminf(fmaxf(u_, 0.f), (float)(WW - 1));
    float vc = fminf(fmaxf(v_, 0.f), (float)(HH - 1));
    float u0f = floorf(uc), v0f = floorf(vc);
    float wu = FSUB(uc, u0f), wv = FSUB(vc, v0f);
    int u0 = (int)u0f, v0 = (int)v0f;
    int u1 = min(u0 + 1, WW - 1), v1 = min(v0 + 1, HH - 1);
    float omwu = FSUB(1.f, wu), omwv = FSUB(1.f, wv);
    float w00 = FMUL(omwu, omwv), w10 = FMUL(wu, omwv);
    float w01 = FMUL(omwu, wv),   w11 = FMUL(wu, wv);

    float da = d1p[v0 * WW + u0], db_ = d1p[v0 * WW + u1];
    float dc = d1p[v1 * WW + u0], dd = d1p[v1 * WW + u1];

    float pxa = FDIV(FSUB((float)u0, cx), fx);
    float pxb = FDIV(FSUB((float)u1, cx), fx);
    float pya = FDIV(FSUB((float)v0, cy), fy);
    float pyb = FDIV(FSUB((float)v1, cy), fy);

    float rVx = FADD(FADD(FADD(FMUL(FMUL(pxa,da), w00), FMUL(FMUL(pxb,db_), w10)),
                          FMUL(FMUL(pxa,dc), w01)), FMUL(FMUL(pxb,dd), w11));
    float rVy = FADD(FADD(FADD(FMUL(FMUL(pya,da), w00), FMUL(FMUL(pya,db_), w10)),
                          FMUL(FMUL(pyb,dc), w01)), FMUL(FMUL(pyb,dd), w11));
    float rVz = FADD(FADD(FADD(FMUL(da, w00), FMUL(db_, w10)),
                          FMUL(dc, w01)), FMUL(dd, w11));

    float rN[3];
#pragma unroll
    for (int c = 0; c < 3; c++) {
        const float* np_ = nb + (size_t)c * NPIX;
        rN[c] = FADD(FADD(FADD(FMUL(np_[v0 * WW + u0], w00), FMUL(np_[v0 * WW + u1], w10)),
                          FMUL(np_[v1 * WW + u0], w01)), FMUL(np_[v1 * WW + u1], w11));
    }

    float dfx = FSUB(xw, rVx), dfy = FSUB(yw, rVy), dfz = FSUB(zw, rVz);
    float dn2 = FADD(FADD(FMUL(dfx,dfx), FMUL(dfy,dfy)), FMUL(dfz,dfz));
    float dnorm = __fsqrt_rn(FADD(dn2, 1e-16f));
    bool occ = (!inview) || (dnorm > 0.1f);

    float res = DOT3(rN[0],dfx, rN[1],dfy, rN[2],dfz);
    float N0_ = DOT3(rN[0],R0, rN[1],R3, rN[2],R6);
    float N1_ = DOT3(rN[0],R1, rN[1],R4, rN[2],R7);
    float N2_ = DOT3(rN[0],R2, rN[1],R5, rN[2],R8);

    float ndot = fabsf(DOT3(rN[0],R2, rN[1],R5, rN[2],R8));
    float dz = FSUB(d0, 0.4f);
    float sz = FADD(0.0012f, FMUL(0.0019f, FMUL(dz,dz)));
    float sigma = FADD(FMUL(ndot, sz), 0.001f);
    float sigden = FADD(sigma, 1e-8f);
    wres = FDIV(res, sigden);

    float c0 = FSUB(FMUL(N1_,Z0), FMUL(N2_,Y0));
    float c1 = FSUB(FMUL(N2_,X0), FMUL(N0_,Z0));
    float c2 = FSUB(FMUL(N0_,Y0), FMUL(N1_,X0));
    Js[0] = FDIV(-c0, sigden);
    Js[1] = FDIV(-c1, sigden);
    Js[2] = FDIV(-c2, sigden);
    Js[3] = FDIV(N0_, sigden);
    Js[4] = FDIV(N1_, sigden);
    Js[5] = FDIV(N2_, sigden);

    if (occ) {
        wres = 0.f;
#pragma unroll
        for (int i = 0; i < 6; i++) Js[i] = 0.f;
    }
}

// ---- exact reduction: Kahan fp32 + double tree + atomics (near-zero noise) ----
__global__ void __launch_bounds__(EBLK) k_accum_exact(const float* __restrict__ depth0,
                                                      const float* __restrict__ depth1,
                                                      const float* __restrict__ Kc) {
    int b = blockIdx.x / EBLKS_PER_B;
    int base = (blockIdx.x % EBLKS_PER_B) * ECHUNK;

    float fx = Kc[b * 4 + 0], fy = Kc[b * 4 + 1], cx = Kc[b * 4 + 2], cy = Kc[b * 4 + 3];
    float R0 = g_R[b][0], R1 = g_R[b][1], R2 = g_R[b][2];
    float R3 = g_R[b][3], R4 = g_R[b][4], R5 = g_R[b][5];
    float R6 = g_R[b][6], R7 = g_R[b][7], R8 = g_R[b][8];
    float t0 = g_t[b][0], t1 = g_t[b][1], t2 = g_t[b][2];

    const float* d0p = depth0 + (size_t)b * NPIX;
    const float* d1p = depth1 + (size_t)b * NPIX;
    const float* nb  = g_normal1 + (size_t)b * 3 * NPIX;

    float acc_s[27], acc_c[27];
#pragma unroll
    for (int k = 0; k < 27; k++) { acc_s[k] = 0.f; acc_c[k] = 0.f; }

    for (int it = 0; it < EITER; it++) {
        int n = base + it * EBLK + threadIdx.x;
        float Js[6], wres;
        pixel_jw(n, fx, fy, cx, cy, R0,R1,R2,R3,R4,R5,R6,R7,R8,
                 t0,t1,t2, d0p, d1p, nb, Js, wres);

        float vals[27];
        int k = 0;
#pragma unroll
        for (int i = 0; i < 6; i++)
#pragma unroll
            for (int j = i; j < 6; j++) vals[k++] = FMUL(Js[i], Js[j]);
#pragma unroll
        for (int i = 0; i < 6; i++) vals[21 + i] = FMUL(Js[i], wres);

#pragma unroll
        for (int kk = 0; kk < 27; kk++) {
            float xv = vals[kk];
            float tt = FADD(acc_s[kk], xv);
            float ee = FADD(FSUB(acc_s[kk], tt), xv);
            acc_c[kk] = FADD(acc_c[kk], ee);
            acc_s[kk] = tt;
        }
    }

    double tot[27];
#pragma unroll
    for (int kk = 0; kk < 27; kk++) tot[kk] = (double)acc_s[kk] + (double)acc_c[kk];
#pragma unroll
    for (int kk = 0; kk < 27; kk++) {
#pragma unroll
        for (int o = 16; o > 0; o >>= 1)
            tot[kk] += __shfl_down_sync(0xFFFFFFFFu, tot[kk], o);
    }

    __shared__ double sh[8][27];
    int warp = threadIdx.x >> 5, lane = threadIdx.x & 31;
    if (lane == 0) {
#pragma unroll
        for (int kk = 0; kk < 27; kk++) sh[warp][kk] = tot[kk];
    }
    __syncthreads();
    if (threadIdx.x < 27) {
        double s = 0.0;
#pragma unroll
        for (int w = 0; w < 8; w++) s += sh[w][threadIdx.x];
        atomicAdd(&g_acc[b][threadIdx.x], s);
    }
}

// ---- noisy reduction phase 1: per-lane serial chains (bit-identical to the
// monolithic kernel's per-thread loop), spread over BB*16 blocks for SM fill ----
__global__ void __launch_bounds__(PBLK) k_noisy_part(const float* __restrict__ depth0,
                                                     const float* __restrict__ depth1,
                                                     const float* __restrict__ Kc) {
    int b = blockIdx.x / PBLKS_PER_B;
    int t = (blockIdx.x % PBLKS_PER_B) * PBLK + threadIdx.x;   // global lane 0..1023

    float fx = Kc[b * 4 + 0], fy = Kc[b * 4 + 1], cx = Kc[b * 4 + 2], cy = Kc[b * 4 + 3];
    float R0 = g_R[b][0], R1 = g_R[b][1], R2 = g_R[b][2];
    float R3 = g_R[b][3], R4 = g_R[b][4], R5 = g_R[b][5];
    float R6 = g_R[b][6], R7 = g_R[b][7], R8 = g_R[b][8];
    float t0 = g_t[b][0], t1 = g_t[b][1], t2 = g_t[b][2];

    const float* d0p = depth0 + (size_t)b * NPIX;
    const float* d1p = depth1 + (size_t)b * NPIX;
    const float* nb  = g_normal1 + (size_t)b * 3 * NPIX;

    float acc[27];
#pragma unroll
    for (int k = 0; k < 27; k++) acc[k] = 0.f;

    for (int it = 0; it < RITER; it++) {
        int n0 = VEC * t + (RBLK * VEC) * it;
#pragma unroll
        for (int v = 0; v < VEC; v++) {
            float Js[6], wres;
            pixel_jw(n0 + v, fx, fy, cx, cy, R0,R1,R2,R3,R4,R5,R6,R7,R8,
                     t0,t1,t2, d0p, d1p, nb, Js, wres);
            int k = 0;
#pragma unroll
            for (int i = 0; i < 6; i++)
#pragma unroll
                for (int j = i; j < 6; j++) { acc[k] = FADD(acc[k], FMUL(Js[i], Js[j])); k++; }
#pragma unroll
            for (int i = 0; i < 6; i++) acc[21 + i] = FADD(acc[21 + i], FMUL(Js[i], wres));
        }
    }

#pragma unroll
    for (int k = 0; k < 27; k++) g_part[b][t][k] = acc[k];
}

// ---- noisy reduction phase 2: identical fp32 tree over the stored partials ----
__global__ void __launch_bounds__(RBLK) k_noisy_tree() {
    int b = blockIdx.x;
    __shared__ float swarp[32];
    int lane = threadIdx.x & 31, wid = threadIdx.x >> 5;
#pragma unroll 1
    for (int kk = 0; kk < 27; kk++) {
        float s = g_part[b][threadIdx.x][kk];
#pragma unroll
        for (int o = 16; o > 0; o >>= 1)
            s = FADD(s, __shfl_down_sync(0xFFFFFFFFu, s, o));
        if (lane == 0) swarp[wid] = s;
        __syncthreads();
        if (wid == 0) {
            float v = swarp[lane];
#pragma unroll
            for (int o = 16; o > 0; o >>= 1)
                v = FADD(v, __shfl_down_sync(0xFFFFFFFFu, v, o));
            if (lane == 0) g_accN[b][kk] = (double)v;
        }
        __syncthreads();
    }
}

// ---- solve with lambda-mixed accumulators ----
__global__ void k_solve() {
    if (threadIdx.x != 0) return;
    int b = blockIdx.x;

    float A[6][6], gf[6];
    {
        int k = 0;
        for (int i = 0; i < 6; i++)
            for (int j = i; j < 6; j++) {
                double e = g_acc[b][k];
                double nn = g_accN[b][k];
                float v = (float)(e + LAMBDA * (nn - e));
                k++;
                A[i][j] = v; A[j][i] = v;
            }
        for (int i = 0; i < 6; i++) {
            double e = g_acc[b][21 + i];
            double nn = g_accN[b][21 + i];
            gf[i] = (float)(e + LAMBDA * (nn - e));
        }
    }
    float trf = A[0][0];
    for (int i = 1; i < 6; i++) trf = FADD(trf, A[i][i]);
    float lm = FMUL(trf, 1e-6f);
    for (int i = 0; i < 6; i++) A[i][i] = FADD(A[i][i], lm);

    int piv[6];
    for (int c = 0; c < 6; c++) {
        int pv = c;
        float amax = fabsf(A[c][c]);
        for (int i = c + 1; i < 6; i++) {
            float av = fabsf(A[i][c]);
            if (av > amax) { amax = av; pv = i; }
        }
        piv[c] = pv;
        if (pv != c)
            for (int j = 0; j < 6; j++) { float tmp = A[c][j]; A[c][j] = A[pv][j]; A[pv][j] = tmp; }
        float pivval = A[c][c];
        for (int i = c + 1; i < 6; i++)
            A[i][c] = FDIV(A[i][c], pivval);
        for (int i = c + 1; i < 6; i++) {
            float l = A[i][c];
            for (int j = c + 1; j < 6; j++)
                A[i][j] = FSUB(A[i][j], FMUL(l, A[c][j]));
        }
    }

    float X[6][6];
    for (int j = 0; j < 6; j++) {
        float bcol[6];
        for (int i = 0; i < 6; i++) bcol[i] = (i == j) ? 1.f : 0.f;
        for (int c = 0; c < 6; c++) {
            int pv = piv[c];
            if (pv != c) { float tmp = bcol[c]; bcol[c] = bcol[pv]; bcol[pv] = tmp; }
        }
        for (int c = 0; c < 6; c++)
            for (int i = c + 1; i < 6; i++)
                bcol[i] = FSUB(bcol[i], FMUL(A[i][c], bcol[c]));
        for (int c = 5; c >= 0; c--) {
            bcol[c] = FDIV(bcol[c], A[c][c]);
            for (int i = 0; i < c; i++)
                bcol[i] = FSUB(bcol[i], FMUL(A[i][c], bcol[c]));
        }
        for (int i = 0; i < 6; i++) X[i][j] = bcol[i];
    }

    float xi[6];
    for (int i = 0; i < 6; i++) {
        float s = FMUL(X[i][0], gf[0]);
        for (int j = 1; j < 6; j++) s = FADD(s, FMUL(X[i][j], gf[j]));
        xi[i] = s;
    }

    float w0 = -xi[0], w1 = -xi[1], w2 = -xi[2];
    float th = __fsqrt_rn(FADD(FADD(FADD(FMUL(w0,w0), FMUL(w1,w1)), FMUL(w2,w2)), 1e-24f));
    float kx = FDIV(w0, th), ky = FDIV(w1, th), kz = FDIV(w2, th);
    float st = sinf(th);
    float omc = FSUB(1.f, cosf(th));
    float Kv[3][3] = {{0.f, -kz, ky}, {kz, 0.f, -kx}, {-ky, kx, 0.f}};
    float K2[3][3];
    for (int i = 0; i < 3; i++)
        for (int j = 0; j < 3; j++)
            K2[i][j] = DOT3(Kv[i][0],Kv[0][j], Kv[i][1],Kv[1][j], Kv[i][2],Kv[2][j]);
    float dR[3][3];
    for (int i = 0; i < 3; i++)
        for (int j = 0; j < 3; j++) {
            float e = (i == j) ? 1.f : 0.f;
            dR[i][j] = FADD(FADD(e, FMUL(st, Kv[i][j])), FMUL(omc, K2[i][j]));
        }

    float dt[3];
    for (int i = 0; i < 3; i++)
        dt[i] = -DOT3(dR[i][0],xi[3], dR[i][1],xi[4], dR[i][2],xi[5]);

    float Ro[3][3], to[3];
    for (int i = 0; i < 3; i++) {
        for (int j = 0; j < 3; j++) Ro[i][j] = g_R[b][i * 3 + j];
        to[i] = g_t[b][i];
    }
    for (int i = 0; i < 3; i++) {
        for (int j = 0; j < 3; j++)
            g_R[b][i * 3 + j] = DOT3(Ro[i][0],dR[0][j], Ro[i][1],dR[1][j], Ro[i][2],dR[2][j]);
        float s = DOT3(Ro[i][0],dt[0], Ro[i][1],dt[1], Ro[i][2],dt[2]);
        g_t[b][i] = FADD(s, to[i]);
    }

    for (int i = 0; i < 27; i++) g_acc[b][i] = 0.0;
}

__global__ void k_out(float* __restrict__ out) {
    int i = threadIdx.x;
    if (i < BB * 9) out[i] = g_R[i / 9][i % 9];
    else if (i < BB * 9 + BB * 3) {
        int j = i - BB * 9;
        out[i] = g_t[j / 3][j % 3];
    }
}

extern "C" void kernel_launch(void* const* d_in, const int* in_sizes, int n_in,
                              void* d_out, int out_size) {
    const float* depth0 = (const float*)d_in[0];
    const float* depth1 = (const float*)d_in[1];
    const float* Kc     = (const float*)d_in[2];
    const float* R_in   = (const float*)d_in[3];
    const float* t_in   = (const float*)d_in[4];
    float* out = (float*)d_out;

    k_init<<<1, 512>>>(R_in, t_in);
    k_minmax<<<480, 256>>>(depth1);
    k_normal<<<TOTAL / 256, 256>>>(depth1, Kc, out + BB * 9 + BB * 3);
    for (int it = 0; it < 3; it++) {
        k_accum_exact<<<BB * EBLKS_PER_B, EBLK>>>(depth0, depth1, Kc);
        k_noisy_part<<<BB * PBLKS_PER_B, PBLK>>>(depth0, depth1, Kc);
        k_noisy_tree<<<BB, RBLK>>>();
        k_solve<<<BB, 32>>>();
    }
    k_out<<<1, 256>>>(out);
}